// round 9
// baseline (speedup 1.0000x reference)
#include <cuda_runtime.h>

// IF spiking neuron, T=4. 128 MiB in + 128 MiB out; both streams exceed L2,
// so 268MB DRAM traffic is compulsory and wall = traffic / BW_eff.
// Session plateau: ~6.16 TB/s effective (77% of spec) across all configs.
// R9: R8 champion (v8 ld/st, 512thr, 2048 CTAs) + streaming hint on LOADS only
// (.cs): zero L2 retention for the read stream -> dirty output lines are not
// evicted early by inbound reads. Last untested single-variable cell.

#define TSTEPS 4

struct __align__(32) f8 { float v[8]; };

__device__ __forceinline__ f8 ldg256_cs(const f8* p) {
    f8 r;
    asm volatile("ld.global.cs.v8.f32 {%0,%1,%2,%3,%4,%5,%6,%7}, [%8];"
                 : "=f"(r.v[0]), "=f"(r.v[1]), "=f"(r.v[2]), "=f"(r.v[3]),
                   "=f"(r.v[4]), "=f"(r.v[5]), "=f"(r.v[6]), "=f"(r.v[7])
                 : "l"(p));
    return r;
}

__device__ __forceinline__ void stg256(f8* p, const f8& r) {
    asm volatile("st.global.v8.f32 [%0], {%1,%2,%3,%4,%5,%6,%7,%8};"
                 :: "l"(p),
                    "f"(r.v[0]), "f"(r.v[1]), "f"(r.v[2]), "f"(r.v[3]),
                    "f"(r.v[4]), "f"(r.v[5]), "f"(r.v[6]), "f"(r.v[7])
                 : "memory");
}

__global__ __launch_bounds__(512)
void if_kernel(const f8* __restrict__ x,
               const float* __restrict__ thresh,
               f8* __restrict__ out,
               int stride8)
{
    int i = blockIdx.x * blockDim.x + threadIdx.x;

    const float th = __ldg(thresh);
    const float m0 = 0.5f * th;

    // 4 independent strided 32B loads (128B in flight per thread).
    f8 xt[TSTEPS];
#pragma unroll
    for (int t = 0; t < TSTEPS; t++)
        xt[t] = ldg256_cs(&x[i + t * stride8]);

    // In-place membrane recurrence: 8 independent scalar chains.
#pragma unroll
    for (int c = 0; c < 8; c++) {
        float m = m0;
#pragma unroll
        for (int t = 0; t < TSTEPS; t++) {
            m += xt[t].v[c];
            float s = (m >= th) ? th : 0.0f;
            xt[t].v[c] = s;
            m -= s;
        }
    }

#pragma unroll
    for (int t = 0; t < TSTEPS; t++)
        stg256(&out[i + t * stride8], xt[t]);
}

extern "C" void kernel_launch(void* const* d_in, const int* in_sizes, int n_in,
                              void* d_out, int out_size)
{
    const float* x      = (const float*)d_in[0];
    const float* thresh = (const float*)d_in[1];
    float* out          = (float*)d_out;

    int n = in_sizes[0];              // total elements = 2^27
    int stride = n / TSTEPS;          // elements per timestep slab = 8388608
    int stride8 = stride / 8;         // f8 units per slab = 1048576

    int threads = 512;
    int blocks = stride8 / threads;   // 2048, exact
    if_kernel<<<blocks, threads>>>(
        (const f8*)x, thresh, (f8*)out, stride8);
}

// round 10
// speedup vs baseline: 1.0007x; 1.0007x over previous
#include <cuda_runtime.h>

// IF spiking neuron, T=4. 128 MiB in + 128 MiB out; both streams exceed L2,
// so 268MB DRAM traffic is compulsory; wall = traffic / BW_eff.
// Measured plateau: 6.16 TB/s effective (wall), 6.0-6.1 TB/s in-kernel.
// R10: final shape probe along the only observed gradient (burst length):
// 1024-thread blocks (grid=1024, 32KB contiguous per slab per CTA).
// Everything else identical to the R8 champion (v8 ld/st, MLP=4x32B,
// default cache policy).

#define TSTEPS 4

struct __align__(32) f8 { float v[8]; };

__device__ __forceinline__ f8 ldg256(const f8* p) {
    f8 r;
    asm volatile("ld.global.v8.f32 {%0,%1,%2,%3,%4,%5,%6,%7}, [%8];"
                 : "=f"(r.v[0]), "=f"(r.v[1]), "=f"(r.v[2]), "=f"(r.v[3]),
                   "=f"(r.v[4]), "=f"(r.v[5]), "=f"(r.v[6]), "=f"(r.v[7])
                 : "l"(p));
    return r;
}

__device__ __forceinline__ void stg256(f8* p, const f8& r) {
    asm volatile("st.global.v8.f32 [%0], {%1,%2,%3,%4,%5,%6,%7,%8};"
                 :: "l"(p),
                    "f"(r.v[0]), "f"(r.v[1]), "f"(r.v[2]), "f"(r.v[3]),
                    "f"(r.v[4]), "f"(r.v[5]), "f"(r.v[6]), "f"(r.v[7])
                 : "memory");
}

__global__ __launch_bounds__(1024)
void if_kernel(const f8* __restrict__ x,
               const float* __restrict__ thresh,
               f8* __restrict__ out,
               int stride8)
{
    int i = blockIdx.x * blockDim.x + threadIdx.x;

    const float th = __ldg(thresh);
    const float m0 = 0.5f * th;

    // 4 independent strided 32B loads (128B in flight per thread).
    f8 xt[TSTEPS];
#pragma unroll
    for (int t = 0; t < TSTEPS; t++)
        xt[t] = ldg256(&x[i + t * stride8]);

    // In-place membrane recurrence: 8 independent scalar chains.
#pragma unroll
    for (int c = 0; c < 8; c++) {
        float m = m0;
#pragma unroll
        for (int t = 0; t < TSTEPS; t++) {
            m += xt[t].v[c];
            float s = (m >= th) ? th : 0.0f;
            xt[t].v[c] = s;
            m -= s;
        }
    }

#pragma unroll
    for (int t = 0; t < TSTEPS; t++)
        stg256(&out[i + t * stride8], xt[t]);
}

extern "C" void kernel_launch(void* const* d_in, const int* in_sizes, int n_in,
                              void* d_out, int out_size)
{
    const float* x      = (const float*)d_in[0];
    const float* thresh = (const float*)d_in[1];
    float* out          = (float*)d_out;

    int n = in_sizes[0];              // total elements = 2^27
    int stride = n / TSTEPS;          // elements per timestep slab = 8388608
    int stride8 = stride / 8;         // f8 units per slab = 1048576

    int threads = 1024;
    int blocks = stride8 / threads;   // 1024, exact
    if_kernel<<<blocks, threads>>>(
        (const f8*)x, thresh, (f8*)out, stride8);
}